// round 4
// baseline (speedup 1.0000x reference)
#include <cuda_runtime.h>
#include <cstdint>
#include <cstddef>

// Problem constants
#define NN 10000
#define KK 16
#define MEAN_NODES 625.0f

// Main kernel: thread-per-column, broadcast Yn from smem.
#define THREADS 1024
#define NBLK_J 10                   // 10 x 1024 columns = 10240 >= 10000
#define NBLK_I 14
#define IT 715                      // 14 x 715 = 10010 >= 10000
#define GRID_MAIN (NBLK_J * NBLK_I) // 140 blocks = one wave
#define PBLOCKS 40

// Device-global scratch
__device__ double g_cut;
__device__ float  g_invg[KK];
__device__ float  g_ep;
__device__ float  g_part[PBLOCKS * 32];
__device__ unsigned int g_ctr_p;
__device__ unsigned int g_ctr_m;

// ---- packed f32x2 helpers (Blackwell FFMA2) ----
__device__ __forceinline__ unsigned long long ffma2(unsigned long long a,
                                                    unsigned long long b,
                                                    unsigned long long c) {
    unsigned long long d;
    asm("fma.rn.f32x2 %0, %1, %2, %3;" : "=l"(d) : "l"(a), "l"(b), "l"(c));
    return d;
}
__device__ __forceinline__ unsigned long long pack2(float x, float y) {
    unsigned long long d;
    asm("mov.b64 %0, {%1, %2};" : "=l"(d) : "f"(x), "f"(y));
    return d;
}
__device__ __forceinline__ float2 unpack2(unsigned long long v) {
    float2 r;
    asm("mov.b64 {%0, %1}, %2;" : "=f"(r.x), "=f"(r.y) : "l"(v));
    return r;
}

// ============================================================
// Kernel 1: partials of gamma[k]=sum Y[i,k]*deg[i], colsum[k]=sum Y[i,k];
// last block finalizes g_invg, g_ep, zeroes g_cut.
// ============================================================
__global__ void k_partial(const float* __restrict__ Y,
                          const float* __restrict__ deg) {
    int i = blockIdx.x * 256 + threadIdx.x;
    float g[KK], c[KK];
#pragma unroll
    for (int k = 0; k < KK; k++) { g[k] = 0.f; c[k] = 0.f; }

    if (i < NN) {
        float d = deg[i];
        const float4* yr = (const float4*)(Y + (size_t)i * KK);
#pragma unroll
        for (int q = 0; q < 4; q++) {
            float4 v = yr[q];
            c[q * 4 + 0] = v.x; c[q * 4 + 1] = v.y;
            c[q * 4 + 2] = v.z; c[q * 4 + 3] = v.w;
            g[q * 4 + 0] = v.x * d; g[q * 4 + 1] = v.y * d;
            g[q * 4 + 2] = v.z * d; g[q * 4 + 3] = v.w * d;
        }
    }
#pragma unroll
    for (int k = 0; k < KK; k++) {
#pragma unroll
        for (int o = 16; o; o >>= 1) {
            g[k] += __shfl_xor_sync(0xffffffffu, g[k], o);
            c[k] += __shfl_xor_sync(0xffffffffu, c[k], o);
        }
    }
    __shared__ float red[8][32];
    __shared__ bool  is_last;
    int warp = threadIdx.x >> 5, lane = threadIdx.x & 31;
    if (lane == 0) {
#pragma unroll
        for (int k = 0; k < KK; k++) {
            red[warp][k]      = g[k];
            red[warp][16 + k] = c[k];
        }
    }
    __syncthreads();
    if (threadIdx.x < 32) {
        float s = 0.f;
#pragma unroll
        for (int w = 0; w < 8; w++) s += red[w][threadIdx.x];
        g_part[blockIdx.x * 32 + threadIdx.x] = s;
    }
    __threadfence();
    if (threadIdx.x == 0) {
        unsigned int old = atomicAdd(&g_ctr_p, 1u);
        is_last = (old == PBLOCKS - 1);
    }
    __syncthreads();
    if (is_last && threadIdx.x < 32) {
        __threadfence();
        int t = threadIdx.x;
        const volatile float* gp = g_part;
        float s = 0.f;
        for (int b = 0; b < PBLOCKS; b++) s += gp[b * 32 + t];
        red[0][t] = s;
        __syncwarp();
        if (t < KK) g_invg[t] = 1.0f / s;
        if (t == 0) {
            float e = 0.f;
#pragma unroll
            for (int k = 0; k < KK; k++) {
                float d2 = red[0][16 + k] - MEAN_NODES;
                e += d2 * d2;
            }
            g_ep   = e;
            g_cut  = 0.0;
            g_ctr_p = 0u;
        }
    }
}

// ============================================================
// Kernel 2: main pass. Thread owns column j; accumulates
//   acc_j[k] = sum_{i in tile} A[i,j] * Yn[i,k]   (Yn broadcast from smem)
// epilogue: part = dot(acc_j, 1 - Y[j,:]); block reduce -> g_cut.
// ============================================================
__global__ void __launch_bounds__(THREADS, 1)
k_main(const float* __restrict__ A, const float* __restrict__ Y,
       float* __restrict__ out) {
    __shared__ float sYn[IT * KK];   // 45,760 B

    const int tid  = threadIdx.x;
    const int col  = blockIdx.x * THREADS + tid;
    const int colc = col < NN ? col : NN - 1;     // clamped (safe) address
    const bool active = col < NN;
    const int i0   = blockIdx.y * IT;
    const int iend = (NN - i0 < IT) ? (NN - i0) : IT;

    // ---- cooperative Yn tile load: yn[i,k] = Y[i,k] * invg[k] ----
    float4 iv[4];
#pragma unroll
    for (int q = 0; q < 4; q++)
        iv[q] = *(const float4*)(g_invg + q * 4);

    for (int idx = tid; idx < IT * 4; idx += THREADS) {
        int r = idx >> 2, c = idx & 3;
        int i = i0 + r;
        float4 v = make_float4(0.f, 0.f, 0.f, 0.f);
        if (i < NN) {
            float4 y = *(const float4*)(Y + (size_t)i * KK + c * 4);
            v = make_float4(y.x * iv[c].x, y.y * iv[c].y,
                            y.z * iv[c].z, y.w * iv[c].w);
        }
        *(float4*)(sYn + r * KK + c * 4) = v;
    }
    __syncthreads();

    // ---- main i-loop: groups of 8 rows, double-buffered A loads ----
    unsigned long long acc[8];
#pragma unroll
    for (int p = 0; p < 8; p++) acc[p] = 0ULL;

    const int imain = iend & ~7;
    const float* aprow = A + (size_t)i0 * NN + colc;   // row i0, this column

    float cur[8];
    if (imain > 0) {
#pragma unroll
        for (int ii = 0; ii < 8; ii++)
            cur[ii] = __ldcs(aprow + (size_t)ii * NN);
    }

    const float* syn = sYn;
#pragma unroll 1
    for (int i = 0; i < imain; i += 8) {
        // prefetch next group (predicated; uniform condition)
        const bool more = (i + 8) < imain;
        const float* apn = aprow + (size_t)(i + 8) * NN;
        float nxt[8];
#pragma unroll
        for (int ii = 0; ii < 8; ii++)
            nxt[ii] = more ? __ldcs(apn + (size_t)ii * NN) : 0.f;

#pragma unroll
        for (int ii = 0; ii < 8; ii++) {
            const ulonglong2* yp = (const ulonglong2*)(syn + ii * KK);
            ulonglong2 y0 = yp[0], y1 = yp[1], y2 = yp[2], y3 = yp[3];
            unsigned long long ap2 = pack2(cur[ii], cur[ii]);
            acc[0] = ffma2(ap2, y0.x, acc[0]);
            acc[1] = ffma2(ap2, y0.y, acc[1]);
            acc[2] = ffma2(ap2, y1.x, acc[2]);
            acc[3] = ffma2(ap2, y1.y, acc[3]);
            acc[4] = ffma2(ap2, y2.x, acc[4]);
            acc[5] = ffma2(ap2, y2.y, acc[5]);
            acc[6] = ffma2(ap2, y3.x, acc[6]);
            acc[7] = ffma2(ap2, y3.y, acc[7]);
        }
#pragma unroll
        for (int ii = 0; ii < 8; ii++) cur[ii] = nxt[ii];
        syn += 8 * KK;
    }

    // tail rows (uniform per block, <= 7)
    for (int i = imain; i < iend; i++) {
        float a = __ldcs(aprow + (size_t)i * NN);
        const ulonglong2* yp = (const ulonglong2*)(sYn + i * KK);
        ulonglong2 y0 = yp[0], y1 = yp[1], y2 = yp[2], y3 = yp[3];
        unsigned long long ap2 = pack2(a, a);
        acc[0] = ffma2(ap2, y0.x, acc[0]);
        acc[1] = ffma2(ap2, y0.y, acc[1]);
        acc[2] = ffma2(ap2, y1.x, acc[2]);
        acc[3] = ffma2(ap2, y1.y, acc[3]);
        acc[4] = ffma2(ap2, y2.x, acc[4]);
        acc[5] = ffma2(ap2, y2.y, acc[5]);
        acc[6] = ffma2(ap2, y3.x, acc[6]);
        acc[7] = ffma2(ap2, y3.y, acc[7]);
    }

    // ---- epilogue: part = dot(acc, 1 - Y[col,:]) ----
    float part = 0.f;
    if (active) {
        const float4* wy = (const float4*)(Y + (size_t)col * KK);
#pragma unroll
        for (int q = 0; q < 4; q++) {
            float4 y = wy[q];
            float2 u0 = unpack2(acc[q * 2]);
            float2 u1 = unpack2(acc[q * 2 + 1]);
            part += u0.x * (1.f - y.x) + u0.y * (1.f - y.y)
                  + u1.x * (1.f - y.z) + u1.y * (1.f - y.w);
        }
    }

    // warp reduce + one double atomic per warp
#pragma unroll
    for (int o = 16; o; o >>= 1) part += __shfl_xor_sync(0xffffffffu, part, o);
    if ((tid & 31) == 0) atomicAdd(&g_cut, (double)part);

    // last block writes the scalar output
    __shared__ bool is_last;
    __threadfence();
    __syncthreads();
    if (tid == 0) {
        unsigned int old = atomicAdd(&g_ctr_m, 1u);
        is_last = (old == GRID_MAIN - 1);
    }
    __syncthreads();
    if (is_last && tid == 0) {
        __threadfence();
        double cut = *((volatile double*)&g_cut);
        out[0] = (float)(cut + (double)g_ep);
        g_ctr_m = 0u;
    }
}

extern "C" void kernel_launch(void* const* d_in, const int* in_sizes, int n_in,
                              void* d_out, int out_size) {
    const float* Y   = (const float*)d_in[0];   // [N, K]
    const float* A   = (const float*)d_in[1];   // [N, N]
    const float* deg = (const float*)d_in[2];   // [N, 1]
    float* out = (float*)d_out;

    k_partial<<<PBLOCKS, 256>>>(Y, deg);
    dim3 grid(NBLK_J, NBLK_I);
    k_main<<<grid, THREADS>>>(A, Y, out);
}

// round 5
// speedup vs baseline: 1.3465x; 1.3465x over previous
#include <cuda_runtime.h>
#include <cstdint>
#include <cstddef>

// Problem constants
#define NN 10000
#define KK 16
#define MEAN_NODES 625.0f

// Main kernel: 2 adjacent columns per thread, broadcast yn row from smem.
#define THREADS 768
#define CPT 2
#define COLS_PER_BLOCK (THREADS * CPT)   // 1536
#define NBLK_J 7                         // 7 * 1536 = 10752 >= 10000
#define NBLK_I 21
#define IT 477                           // 21 * 477 = 10017 >= 10000
#define GRID_MAIN (NBLK_J * NBLK_I)      // 147 blocks = one wave
#define GROUP 4                          // rows per inner group (double-buffered)
#define PBLOCKS 40

// Device-global scratch
__device__ double g_cut;
__device__ float  g_invg[KK];
__device__ float  g_ep;
__device__ float  g_part[PBLOCKS * 32];
__device__ unsigned int g_ctr_p;
__device__ unsigned int g_ctr_m;

// ---- packed f32x2 helpers (Blackwell FFMA2) ----
__device__ __forceinline__ unsigned long long ffma2(unsigned long long a,
                                                    unsigned long long b,
                                                    unsigned long long c) {
    unsigned long long d;
    asm("fma.rn.f32x2 %0, %1, %2, %3;" : "=l"(d) : "l"(a), "l"(b), "l"(c));
    return d;
}
__device__ __forceinline__ unsigned long long pack2(float x, float y) {
    unsigned long long d;
    asm("mov.b64 %0, {%1, %2};" : "=l"(d) : "f"(x), "f"(y));
    return d;
}
__device__ __forceinline__ float2 unpack2(unsigned long long v) {
    float2 r;
    asm("mov.b64 {%0, %1}, %2;" : "=f"(r.x), "=f"(r.y) : "l"(v));
    return r;
}

// ============================================================
// Kernel 1: partials of gamma[k]=sum Y[i,k]*deg[i], colsum[k]=sum Y[i,k];
// last block finalizes g_invg, g_ep, zeroes g_cut.
// ============================================================
__global__ void k_partial(const float* __restrict__ Y,
                          const float* __restrict__ deg) {
    int i = blockIdx.x * 256 + threadIdx.x;
    float g[KK], c[KK];
#pragma unroll
    for (int k = 0; k < KK; k++) { g[k] = 0.f; c[k] = 0.f; }

    if (i < NN) {
        float d = deg[i];
        const float4* yr = (const float4*)(Y + (size_t)i * KK);
#pragma unroll
        for (int q = 0; q < 4; q++) {
            float4 v = yr[q];
            c[q * 4 + 0] = v.x; c[q * 4 + 1] = v.y;
            c[q * 4 + 2] = v.z; c[q * 4 + 3] = v.w;
            g[q * 4 + 0] = v.x * d; g[q * 4 + 1] = v.y * d;
            g[q * 4 + 2] = v.z * d; g[q * 4 + 3] = v.w * d;
        }
    }
#pragma unroll
    for (int k = 0; k < KK; k++) {
#pragma unroll
        for (int o = 16; o; o >>= 1) {
            g[k] += __shfl_xor_sync(0xffffffffu, g[k], o);
            c[k] += __shfl_xor_sync(0xffffffffu, c[k], o);
        }
    }
    __shared__ float red[8][32];
    __shared__ bool  is_last;
    int warp = threadIdx.x >> 5, lane = threadIdx.x & 31;
    if (lane == 0) {
#pragma unroll
        for (int k = 0; k < KK; k++) {
            red[warp][k]      = g[k];
            red[warp][16 + k] = c[k];
        }
    }
    __syncthreads();
    if (threadIdx.x < 32) {
        float s = 0.f;
#pragma unroll
        for (int w = 0; w < 8; w++) s += red[w][threadIdx.x];
        g_part[blockIdx.x * 32 + threadIdx.x] = s;
    }
    __threadfence();
    if (threadIdx.x == 0) {
        unsigned int old = atomicAdd(&g_ctr_p, 1u);
        is_last = (old == PBLOCKS - 1);
    }
    __syncthreads();
    if (is_last && threadIdx.x < 32) {
        __threadfence();
        int t = threadIdx.x;
        const volatile float* gp = g_part;
        float s = 0.f;
        for (int b = 0; b < PBLOCKS; b++) s += gp[b * 32 + t];
        red[0][t] = s;
        __syncwarp();
        if (t < KK) g_invg[t] = 1.0f / s;
        if (t == 0) {
            float e = 0.f;
#pragma unroll
            for (int k = 0; k < KK; k++) {
                float d2 = red[0][16 + k] - MEAN_NODES;
                e += d2 * d2;
            }
            g_ep   = e;
            g_cut  = 0.0;
            g_ctr_p = 0u;
        }
    }
}

// ============================================================
// Kernel 2: main pass. Thread owns column pair (c0, c0+1):
//   acc[c][k] += A[i, c0+c] * yn[i,k]   (yn row broadcast from smem)
// epilogue: part = sum_c dot(acc[c], 1 - Y[c0+c,:]).
// ============================================================
__global__ void __launch_bounds__(THREADS, 1)
k_main(const float* __restrict__ A, const float* __restrict__ Y,
       float* __restrict__ out) {
    __shared__ float sYn[IT * KK];   // 30,528 B

    const int tid  = threadIdx.x;
    const int col0 = blockIdx.x * COLS_PER_BLOCK + 2 * tid;
    const int colc = col0 <= NN - 2 ? col0 : NN - 2;  // in-bounds clamp
    const int i0   = blockIdx.y * IT;
    const int iend = (NN - i0 < IT) ? (NN - i0) : IT;

    // ---- cooperative yn tile load: yn[i,k] = Y[i,k] * invg[k] ----
    float4 iv[4];
#pragma unroll
    for (int q = 0; q < 4; q++)
        iv[q] = *(const float4*)(g_invg + q * 4);

    for (int idx = tid; idx < IT * 4; idx += THREADS) {
        int r = idx >> 2, c = idx & 3;
        int i = i0 + r;
        float4 v = make_float4(0.f, 0.f, 0.f, 0.f);
        if (i < NN) {
            float4 y = *(const float4*)(Y + (size_t)i * KK + c * 4);
            v = make_float4(y.x * iv[c].x, y.y * iv[c].y,
                            y.z * iv[c].z, y.w * iv[c].w);
        }
        *(float4*)(sYn + r * KK + c * 4) = v;
    }
    __syncthreads();

    // ---- main i-loop: groups of 4 rows, double-buffered LDG.64 ----
    unsigned long long acc0[8], acc1[8];
#pragma unroll
    for (int p = 0; p < 8; p++) { acc0[p] = 0ULL; acc1[p] = 0ULL; }

    const int imain = iend & ~(GROUP - 1);
    const float* ap = A + (size_t)i0 * NN + colc;

    float2 cur[GROUP];
    if (imain > 0) {
#pragma unroll
        for (int g = 0; g < GROUP; g++)
            cur[g] = __ldcs((const float2*)(ap + (size_t)g * NN));
    }

    const float* syn = sYn;
#pragma unroll 1
    for (int i = 0; i < imain; i += GROUP) {
        const bool more = (i + GROUP) < imain;
        const float* apn = ap + (size_t)GROUP * NN;
        float2 nxt[GROUP];
#pragma unroll
        for (int g = 0; g < GROUP; g++)
            nxt[g] = more ? __ldcs((const float2*)(apn + (size_t)g * NN))
                          : make_float2(0.f, 0.f);

#pragma unroll
        for (int g = 0; g < GROUP; g++) {
            const ulonglong2* yp = (const ulonglong2*)(syn + g * KK);
            ulonglong2 y0 = yp[0], y1 = yp[1], y2 = yp[2], y3 = yp[3];
            unsigned long long a0 = pack2(cur[g].x, cur[g].x);
            unsigned long long a1 = pack2(cur[g].y, cur[g].y);
            acc0[0] = ffma2(a0, y0.x, acc0[0]);
            acc0[1] = ffma2(a0, y0.y, acc0[1]);
            acc0[2] = ffma2(a0, y1.x, acc0[2]);
            acc0[3] = ffma2(a0, y1.y, acc0[3]);
            acc0[4] = ffma2(a0, y2.x, acc0[4]);
            acc0[5] = ffma2(a0, y2.y, acc0[5]);
            acc0[6] = ffma2(a0, y3.x, acc0[6]);
            acc0[7] = ffma2(a0, y3.y, acc0[7]);
            acc1[0] = ffma2(a1, y0.x, acc1[0]);
            acc1[1] = ffma2(a1, y0.y, acc1[1]);
            acc1[2] = ffma2(a1, y1.x, acc1[2]);
            acc1[3] = ffma2(a1, y1.y, acc1[3]);
            acc1[4] = ffma2(a1, y2.x, acc1[4]);
            acc1[5] = ffma2(a1, y2.y, acc1[5]);
            acc1[6] = ffma2(a1, y3.x, acc1[6]);
            acc1[7] = ffma2(a1, y3.y, acc1[7]);
        }
#pragma unroll
        for (int g = 0; g < GROUP; g++) cur[g] = nxt[g];
        ap  += (size_t)GROUP * NN;
        syn += GROUP * KK;
    }

    // tail rows (<= GROUP-1, uniform per block)
    for (int i = imain; i < iend; i++) {
        float2 a = __ldcs((const float2*)(A + (size_t)(i0 + i) * NN + colc));
        const ulonglong2* yp = (const ulonglong2*)(sYn + i * KK);
        ulonglong2 y0 = yp[0], y1 = yp[1], y2 = yp[2], y3 = yp[3];
        unsigned long long a0 = pack2(a.x, a.x);
        unsigned long long a1 = pack2(a.y, a.y);
        acc0[0] = ffma2(a0, y0.x, acc0[0]);
        acc0[1] = ffma2(a0, y0.y, acc0[1]);
        acc0[2] = ffma2(a0, y1.x, acc0[2]);
        acc0[3] = ffma2(a0, y1.y, acc0[3]);
        acc0[4] = ffma2(a0, y2.x, acc0[4]);
        acc0[5] = ffma2(a0, y2.y, acc0[5]);
        acc0[6] = ffma2(a0, y3.x, acc0[6]);
        acc0[7] = ffma2(a0, y3.y, acc0[7]);
        acc1[0] = ffma2(a1, y0.x, acc1[0]);
        acc1[1] = ffma2(a1, y0.y, acc1[1]);
        acc1[2] = ffma2(a1, y1.x, acc1[2]);
        acc1[3] = ffma2(a1, y1.y, acc1[3]);
        acc1[4] = ffma2(a1, y2.x, acc1[4]);
        acc1[5] = ffma2(a1, y2.y, acc1[5]);
        acc1[6] = ffma2(a1, y3.x, acc1[6]);
        acc1[7] = ffma2(a1, y3.y, acc1[7]);
    }

    // ---- epilogue: part = sum over owned valid columns ----
    float part = 0.f;
    if (col0 < NN) {
        const float4* wy = (const float4*)(Y + (size_t)col0 * KK);
#pragma unroll
        for (int q = 0; q < 4; q++) {
            float4 y = wy[q];
            float2 u0 = unpack2(acc0[q * 2]);
            float2 u1 = unpack2(acc0[q * 2 + 1]);
            part += u0.x * (1.f - y.x) + u0.y * (1.f - y.y)
                  + u1.x * (1.f - y.z) + u1.y * (1.f - y.w);
        }
    }
    if (col0 + 1 < NN) {
        const float4* wy = (const float4*)(Y + (size_t)(col0 + 1) * KK);
#pragma unroll
        for (int q = 0; q < 4; q++) {
            float4 y = wy[q];
            float2 u0 = unpack2(acc1[q * 2]);
            float2 u1 = unpack2(acc1[q * 2 + 1]);
            part += u0.x * (1.f - y.x) + u0.y * (1.f - y.y)
                  + u1.x * (1.f - y.z) + u1.y * (1.f - y.w);
        }
    }

    // warp reduce + one double atomic per warp
#pragma unroll
    for (int o = 16; o; o >>= 1) part += __shfl_xor_sync(0xffffffffu, part, o);
    if ((tid & 31) == 0) atomicAdd(&g_cut, (double)part);

    // last block writes the scalar output
    __shared__ bool is_last;
    __threadfence();
    __syncthreads();
    if (tid == 0) {
        unsigned int old = atomicAdd(&g_ctr_m, 1u);
        is_last = (old == GRID_MAIN - 1);
    }
    __syncthreads();
    if (is_last && tid == 0) {
        __threadfence();
        double cut = *((volatile double*)&g_cut);
        out[0] = (float)(cut + (double)g_ep);
        g_ctr_m = 0u;
    }
}

extern "C" void kernel_launch(void* const* d_in, const int* in_sizes, int n_in,
                              void* d_out, int out_size) {
    const float* Y   = (const float*)d_in[0];   // [N, K]
    const float* A   = (const float*)d_in[1];   // [N, N]
    const float* deg = (const float*)d_in[2];   // [N, 1]
    float* out = (float*)d_out;

    k_partial<<<PBLOCKS, 256>>>(Y, deg);
    dim3 grid(NBLK_J, NBLK_I);
    k_main<<<grid, THREADS>>>(A, Y, out);
}